// round 11
// baseline (speedup 1.0000x reference)
#include <cuda_runtime.h>

// QuantizedTopKSparsity == out[r,c] = rint( x[r,c] / (max_c |x[r,c]| + 1e-6) )
// (x/(gamma+eps) ∈ (-1,1) strictly -> x_q ∈ {-1,0,+1} -> top-k mask is an
//  identity on x_q; see earlier rounds for the proof.)
//
// Round-11: last untried corner — plain grid-stride persistence at LOW regs.
// R2's persistent kernel lost because software pipelining doubled registers
// (64 regs -> occ 47%). This keeps the measured-best R5 body verbatim
// (256 thr, 2 x 256-bit LDG evict_last / STG evict_first, 32 regs, occ ~90%)
// and only wraps it in a row-stride loop: grid 8192 -> 1184 CTAs, removing
// ~7000 CTA launch/drain events and the ragged 6.9-wave tail. Parity-indexed
// smem max slots keep it at ONE barrier per row.

#define ROW_LEN 4096
#define THREADS 256
#define V8 2   // 2 x 8 floats = 16 floats per thread; 256*16 = 4096
#define NWARPS (THREADS / 32)
#define NUM_SMS 148
#define CTAS_PER_SM 8

struct F8 { float a, b, c, d, e, f, g, h; };

__device__ __forceinline__ F8 ld_persist8(const void* p) {
    F8 v;
    asm volatile("ld.global.L2::evict_last.v8.b32 "
                 "{%0,%1,%2,%3,%4,%5,%6,%7}, [%8];"
                 : "=f"(v.a), "=f"(v.b), "=f"(v.c), "=f"(v.d),
                   "=f"(v.e), "=f"(v.f), "=f"(v.g), "=f"(v.h)
                 : "l"(p));
    return v;
}

__device__ __forceinline__ void st_stream8(void* p, const F8& v) {
    asm volatile("st.global.L2::evict_first.v8.b32 "
                 "[%0], {%1,%2,%3,%4,%5,%6,%7,%8};"
                 :: "l"(p),
                    "f"(v.a), "f"(v.b), "f"(v.c), "f"(v.d),
                    "f"(v.e), "f"(v.f), "f"(v.g), "f"(v.h)
                 : "memory");
}

__device__ __forceinline__ float absmax8(const F8& v) {
    float m0 = fmaxf(fmaxf(fabsf(v.a), fabsf(v.b)), fmaxf(fabsf(v.c), fabsf(v.d)));
    float m1 = fmaxf(fmaxf(fabsf(v.e), fabsf(v.f)), fmaxf(fabsf(v.g), fabsf(v.h)));
    return fmaxf(m0, m1);
}

__device__ __forceinline__ F8 quant8(const F8& v, float inv) {
    F8 o;
    o.a = rintf(v.a * inv); o.b = rintf(v.b * inv);
    o.c = rintf(v.c * inv); o.d = rintf(v.d * inv);
    o.e = rintf(v.e * inv); o.f = rintf(v.f * inv);
    o.g = rintf(v.g * inv); o.h = rintf(v.h * inv);
    return o;
}

__global__ __launch_bounds__(THREADS, CTAS_PER_SM)
void qtopk_kernel(const float* __restrict__ x, float* __restrict__ out, int rows) {
    const int t = threadIdx.x;
    const int stride = gridDim.x;

    __shared__ float smax[2][NWARPS];
    int par = 0;

    for (int row = blockIdx.x; row < rows; row += stride, par ^= 1) {
        const float* __restrict__ xr = x   + (size_t)row * ROW_LEN;
        float* __restrict__ orr      = out + (size_t)row * ROW_LEN;

        // Two 256-bit persisting loads per thread, coalesced 32B stripes.
        F8 v[V8];
#pragma unroll
        for (int i = 0; i < V8; i++)
            v[i] = ld_persist8(xr + (t + i * THREADS) * 8);

        float m = 0.0f;
#pragma unroll
        for (int i = 0; i < V8; i++) m = fmaxf(m, absmax8(v[i]));

        // Warp absmax.
#pragma unroll
        for (int o = 16; o > 0; o >>= 1)
            m = fmaxf(m, __shfl_xor_sync(0xffffffffu, m, o));

        // Cross-warp absmax: parity-indexed slots -> one barrier per row,
        // no WAR hazard with the previous iteration's reads.
        if ((t & 31) == 0) smax[par][t >> 5] = m;
        __syncthreads();

        float g = smax[par][0];
#pragma unroll
        for (int w = 1; w < NWARPS; w++) g = fmaxf(g, smax[par][w]);

        const float inv = 1.0f / (g + 1e-6f);

        // Quantize from registers; 256-bit evict-first stores.
#pragma unroll
        for (int i = 0; i < V8; i++)
            st_stream8(orr + (t + i * THREADS) * 8, quant8(v[i], inv));
    }
}

extern "C" void kernel_launch(void* const* d_in, const int* in_sizes, int n_in,
                              void* d_out, int out_size) {
    const float* x = (const float*)d_in[0];
    float* out = (float*)d_out;
    const int rows = in_sizes[0] / ROW_LEN;   // 8192
    int grid = NUM_SMS * CTAS_PER_SM;         // 1184 — one resident wave
    if (grid > rows) grid = rows;
    qtopk_kernel<<<grid, THREADS>>>(x, out, rows);
}

// round 12
// speedup vs baseline: 1.0949x; 1.0949x over previous
#include <cuda_runtime.h>

// QuantizedTopKSparsity == out[r,c] = rint( x[r,c] / (max_c |x[r,c]| + 1e-6) )
// Identity proof: x/(gamma+eps) ∈ (-1,1) strictly, so x_q = round(...) ∈
// {-1,0,+1} and abs_q ∈ {0,1}. A top-k threshold on a {0,1} vector is 0 or 1;
// in both cases x_q * mask == x_q — the entire top-k machinery is an identity.
//
// FINAL kernel — measured optimum over an 11-round sweep:
//   - one 4096-float row per CTA (grid=8192, independent CTAs — persistence
//     in any form serializes loads behind the per-row barrier and loses)
//   - 256 threads, 2 x 256-bit LDG (L2::evict_last) + 2 x 256-bit STG
//     (L2::evict_first) per thread, coalesced 32B stripes, 32 regs, occ ~90%
//   - shuffle warp absmax + 8-warp smem combine, single barrier
// Bound: memory-path ceiling for interleaved 1:1 R/W (~5.9-6.0 TB/s, ~75% of
// 8TB/s spec). Swept and rejected: block 128/512, 1/4 loads per thread,
// grid-stride + pipelined persistence, all cache policies, REDUX reduce.
// SM pipes <10% busy throughout — nothing on-chip binds.

#define ROW_LEN 4096
#define THREADS 256
#define V8 2   // 2 x 8 floats = 16 floats per thread; 256*16 = 4096
#define NWARPS (THREADS / 32)

struct F8 { float a, b, c, d, e, f, g, h; };

__device__ __forceinline__ F8 ld_persist8(const void* p) {
    F8 v;
    asm volatile("ld.global.L2::evict_last.v8.b32 "
                 "{%0,%1,%2,%3,%4,%5,%6,%7}, [%8];"
                 : "=f"(v.a), "=f"(v.b), "=f"(v.c), "=f"(v.d),
                   "=f"(v.e), "=f"(v.f), "=f"(v.g), "=f"(v.h)
                 : "l"(p));
    return v;
}

__device__ __forceinline__ void st_stream8(void* p, const F8& v) {
    asm volatile("st.global.L2::evict_first.v8.b32 "
                 "[%0], {%1,%2,%3,%4,%5,%6,%7,%8};"
                 :: "l"(p),
                    "f"(v.a), "f"(v.b), "f"(v.c), "f"(v.d),
                    "f"(v.e), "f"(v.f), "f"(v.g), "f"(v.h)
                 : "memory");
}

__device__ __forceinline__ float absmax8(const F8& v) {
    float m0 = fmaxf(fmaxf(fabsf(v.a), fabsf(v.b)), fmaxf(fabsf(v.c), fabsf(v.d)));
    float m1 = fmaxf(fmaxf(fabsf(v.e), fabsf(v.f)), fmaxf(fabsf(v.g), fabsf(v.h)));
    return fmaxf(m0, m1);
}

__device__ __forceinline__ F8 quant8(const F8& v, float inv) {
    F8 o;
    o.a = rintf(v.a * inv); o.b = rintf(v.b * inv);
    o.c = rintf(v.c * inv); o.d = rintf(v.d * inv);
    o.e = rintf(v.e * inv); o.f = rintf(v.f * inv);
    o.g = rintf(v.g * inv); o.h = rintf(v.h * inv);
    return o;
}

__global__ __launch_bounds__(THREADS)
void qtopk_kernel(const float* __restrict__ x, float* __restrict__ out, int rows) {
    const int row = blockIdx.x;
    if (row >= rows) return;

    const float* __restrict__ xr = x   + (size_t)row * ROW_LEN;
    float* __restrict__ orr      = out + (size_t)row * ROW_LEN;

    const int t = threadIdx.x;

    // Two 256-bit persisting loads per thread, coalesced 32B stripes.
    F8 v[V8];
#pragma unroll
    for (int i = 0; i < V8; i++)
        v[i] = ld_persist8(xr + (t + i * THREADS) * 8);

    float m = 0.0f;
#pragma unroll
    for (int i = 0; i < V8; i++) m = fmaxf(m, absmax8(v[i]));

    // Warp absmax.
#pragma unroll
    for (int o = 16; o > 0; o >>= 1)
        m = fmaxf(m, __shfl_xor_sync(0xffffffffu, m, o));

    // Cross-warp absmax via smem (8 warps), single barrier.
    __shared__ float smax[NWARPS];
    if ((t & 31) == 0) smax[t >> 5] = m;
    __syncthreads();

    float g = smax[0];
#pragma unroll
    for (int w = 1; w < NWARPS; w++) g = fmaxf(g, smax[w]);

    const float inv = 1.0f / (g + 1e-6f);

    // Quantize from registers; 256-bit evict-first stores.
#pragma unroll
    for (int i = 0; i < V8; i++)
        st_stream8(orr + (t + i * THREADS) * 8, quant8(v[i], inv));
}

extern "C" void kernel_launch(void* const* d_in, const int* in_sizes, int n_in,
                              void* d_out, int out_size) {
    const float* x = (const float*)d_in[0];
    float* out = (float*)d_out;
    const int rows = in_sizes[0] / ROW_LEN;   // 8192
    qtopk_kernel<<<rows, THREADS>>>(x, out, rows);
}